// round 4
// baseline (speedup 1.0000x reference)
#include <cuda_runtime.h>
#include <cuda_fp16.h>
#include <cstdint>

// ---------------- problem sizes ----------------
#define SZ_M 8192   // 4 * 2048 rows of x
#define SZ_N 4096   // out features
#define SZ_K 4096   // in features

// ---------------- GEMM tiling ----------------
#define BM 128
#define BN 256
#define BK 64                 // halves per stage (128 bytes per row)
#define STAGES 4
#define KIT (SZ_K / BK)       // 64
#define NTHREADS 512          // 16 warps: 4(M) x 4(N), warp tile 32x64

// smem per stage: A 128x128B + B 256x128B = 48 KB
#define STAGE_A_BYTES (BM * 128)
#define STAGE_B_BYTES (BN * 128)
#define STAGE_BYTES   (STAGE_A_BYTES + STAGE_B_BYTES)
#define SMEM_TOTAL    (STAGES * STAGE_BYTES)    // 196608

static_assert(SZ_M % BM == 0 && SZ_N % BN == 0 && SZ_K % BK == 0, "tiling");

// ---------------- scratch (no cudaMalloc allowed) ----------------
__device__ __align__(16) __half g_xh[(size_t)SZ_M * SZ_K];   // 64 MB
__device__ __align__(16) __half g_wh[(size_t)SZ_N * SZ_K];   // 32 MB

// ---------------- helpers ----------------
static __device__ __forceinline__ uint32_t smem_u32(const void* p) {
    uint32_t r;
    asm("{ .reg .u64 t; cvta.to.shared.u64 t, %1; cvt.u32.u64 %0, t; }"
        : "=r"(r) : "l"(p));
    return r;
}

static __device__ __forceinline__ void cp16(uint32_t dst, const void* src) {
    asm volatile("cp.async.cg.shared.global [%0], [%1], 16;"
                 :: "r"(dst), "l"(src) : "memory");
}

static __device__ __forceinline__ uint32_t sw128(uint32_t off) {
    return off ^ ((off >> 3) & 0x70);
}

static __device__ __forceinline__ void ldm_x4(uint32_t addr,
    uint32_t& r0, uint32_t& r1, uint32_t& r2, uint32_t& r3) {
    asm volatile("ldmatrix.sync.aligned.m8n8.x4.shared.b16 {%0,%1,%2,%3}, [%4];"
                 : "=r"(r0), "=r"(r1), "=r"(r2), "=r"(r3) : "r"(addr));
}

static __device__ __forceinline__ void mma16816(
    float& d0, float& d1, float& d2, float& d3,
    uint32_t a0, uint32_t a1, uint32_t a2, uint32_t a3,
    uint32_t b0, uint32_t b1) {
    asm volatile(
        "mma.sync.aligned.m16n8k16.row.col.f32.f16.f16.f32 "
        "{%0,%1,%2,%3}, {%4,%5,%6,%7}, {%8,%9}, {%0,%1,%2,%3};"
        : "+f"(d0), "+f"(d1), "+f"(d2), "+f"(d3)
        : "r"(a0), "r"(a1), "r"(a2), "r"(a3), "r"(b0), "r"(b1));
}

// ---------------- fused convert kernel ----------------
#define XC ((size_t)SZ_M * SZ_K / 4)
#define WC ((size_t)SZ_N * SZ_K / 4)

__global__ void __launch_bounds__(256) cvt_all_kernel(
    const float* __restrict__ x, const int* __restrict__ q)
{
    size_t i = (size_t)blockIdx.x * blockDim.x + threadIdx.x;
    if (i < XC) {
        float4 v = reinterpret_cast<const float4*>(x)[i];
        __half2 h0 = __floats2half2_rn(v.x, v.y);
        __half2 h1 = __floats2half2_rn(v.z, v.w);
        uint2 r;
        r.x = *reinterpret_cast<unsigned*>(&h0);
        r.y = *reinterpret_cast<unsigned*>(&h1);
        reinterpret_cast<uint2*>(g_xh)[i] = r;
    } else {
        size_t j = i - XC;
        int4 v = reinterpret_cast<const int4*>(q)[j];
        __half2 h0 = __halves2half2(__int2half_rn(v.x), __int2half_rn(v.y));
        __half2 h1 = __halves2half2(__int2half_rn(v.z), __int2half_rn(v.w));
        uint2 r;
        r.x = *reinterpret_cast<unsigned*>(&h0);
        r.y = *reinterpret_cast<unsigned*>(&h1);
        reinterpret_cast<uint2*>(g_wh)[j] = r;
    }
}

// ---------------- stage loader (512 threads) ----------------
static __device__ __forceinline__ void load_stage(
    uint32_t sb, int s, int m0, int n0, int kt, int tid)
{
    const uint32_t base = sb + (uint32_t)s * STAGE_BYTES;
    const int kh = kt * BK;

    // A: BM*8 = 1024 chunks of 16B, 512 threads -> 2 each
    #pragma unroll
    for (int i = 0; i < (BM * 8) / NTHREADS; i++) {
        int c = tid + i * NTHREADS;
        int row = c >> 3, seg = c & 7;
        uint32_t off = (uint32_t)row * 128 + (uint32_t)seg * 16;
        cp16(base + sw128(off), g_xh + (size_t)(m0 + row) * SZ_K + kh + seg * 8);
    }
    // B: BN*8 = 2048 chunks -> 4 each
    const uint32_t bbase = base + STAGE_A_BYTES;
    #pragma unroll
    for (int i = 0; i < (BN * 8) / NTHREADS; i++) {
        int c = tid + i * NTHREADS;
        int row = c >> 3, seg = c & 7;
        uint32_t off = (uint32_t)row * 128 + (uint32_t)seg * 16;
        cp16(bbase + sw128(off), g_wh + (size_t)(n0 + row) * SZ_K + kh + seg * 8);
    }
}

// ---------------- GEMM kernel ----------------
// 512 threads = 16 warps: wm = wid&3 (4 along M, 32 rows), wn = wid>>2 (4 along N, 64 cols).
// Warp tile 32(M) x 64(N): 2 m-tiles (16) x 8 n-tiles (8), k-step 16.
__global__ void __launch_bounds__(NTHREADS, 1)
gemm_hmma_kernel(const float* __restrict__ wscale,
                 const float* __restrict__ bias,
                 float* __restrict__ out)
{
    extern __shared__ char smem[];
    const uint32_t sb = smem_u32(smem);
    const int tid  = threadIdx.x;
    const int wid  = tid >> 5;
    const int lane = tid & 31;
    const int wm = wid & 3;
    const int wn = wid >> 2;
    const int n0 = blockIdx.x * BN;   // n-fastest: W stays L2-resident
    const int m0 = blockIdx.y * BM;

    const int l7   = lane & 7;
    const int hi8  = (lane >> 3) & 1;
    const int hi16 = lane >> 4;

    // A frag rows: wm*32 + mt*16 + hi8*8 + l7 ; k-byte: ks*32 + hi16*16
    const int arow_base = wm * 32 + hi8 * 8 + l7;
    const int akb_base  = hi16 * 16;
    // B frag rows: wn*64 + np*16 + hi16*8 + l7 ; k-byte: ks*32 + hi8*16
    const int brow_base = wn * 64 + hi16 * 8 + l7;
    const int bkb_base  = hi8 * 16;

    float d[2][8][4];
    #pragma unroll
    for (int i = 0; i < 2; i++)
        #pragma unroll
        for (int j = 0; j < 8; j++)
            #pragma unroll
            for (int c = 0; c < 4; c++) d[i][j][c] = 0.0f;

    // prefetch stages 0..STAGES-2
    #pragma unroll
    for (int s = 0; s < STAGES - 1; s++) {
        load_stage(sb, s, m0, n0, s, tid);
        asm volatile("cp.async.commit_group;" ::: "memory");
    }

    #pragma unroll 1
    for (int kt = 0; kt < KIT; kt++) {
        const int s = kt & (STAGES - 1);
        asm volatile("cp.async.wait_group 2;" ::: "memory");
        __syncthreads();   // stage kt visible; stage kt-1 fully consumed by all warps

        if (kt + STAGES - 1 < KIT)
            load_stage(sb, (kt + STAGES - 1) & (STAGES - 1), m0, n0,
                       kt + STAGES - 1, tid);
        asm volatile("cp.async.commit_group;" ::: "memory");

        const uint32_t abase = sb + (uint32_t)s * STAGE_BYTES;
        const uint32_t bbase = abase + STAGE_A_BYTES;

        #pragma unroll
        for (int ks = 0; ks < BK / 16; ks++) {
            uint32_t a[2][4];
            #pragma unroll
            for (int mt = 0; mt < 2; mt++) {
                uint32_t off = (uint32_t)(arow_base + mt * 16) * 128
                             + (uint32_t)(ks * 32 + akb_base);
                ldm_x4(abase + sw128(off), a[mt][0], a[mt][1], a[mt][2], a[mt][3]);
            }
            uint32_t b[8][2];
            #pragma unroll
            for (int np = 0; np < 4; np++) {
                uint32_t off = (uint32_t)(brow_base + np * 16) * 128
                             + (uint32_t)(ks * 32 + bkb_base);
                uint32_t r0, r1, r2, r3;
                ldm_x4(bbase + sw128(off), r0, r1, r2, r3);
                b[np * 2 + 0][0] = r0; b[np * 2 + 0][1] = r1;
                b[np * 2 + 1][0] = r2; b[np * 2 + 1][1] = r3;
            }
            #pragma unroll
            for (int mt = 0; mt < 2; mt++)
                #pragma unroll
                for (int nt = 0; nt < 8; nt++)
                    mma16816(d[mt][nt][0], d[mt][nt][1], d[mt][nt][2], d[mt][nt][3],
                             a[mt][0], a[mt][1], a[mt][2], a[mt][3],
                             b[nt][0], b[nt][1]);
        }
    }

    // ---------------- epilogue: y = d * scale[col] + bias[col] ----------------
    const int crow = m0 + wm * 32 + (lane >> 2);       // + mt*16 (+8 for c2,c3)
    const int ccol = n0 + wn * 64 + (lane & 3) * 2;    // + nt*8

    float sc[8][2], bi[8][2];
    #pragma unroll
    for (int nt = 0; nt < 8; nt++) {
        sc[nt][0] = __ldg(wscale + ccol + nt * 8);
        sc[nt][1] = __ldg(wscale + ccol + nt * 8 + 1);
        bi[nt][0] = __ldg(bias   + ccol + nt * 8);
        bi[nt][1] = __ldg(bias   + ccol + nt * 8 + 1);
    }

    #pragma unroll
    for (int mt = 0; mt < 2; mt++) {
        #pragma unroll
        for (int nt = 0; nt < 8; nt++) {
            float2 v0, v1;
            v0.x = fmaf(d[mt][nt][0], sc[nt][0], bi[nt][0]);
            v0.y = fmaf(d[mt][nt][1], sc[nt][1], bi[nt][1]);
            v1.x = fmaf(d[mt][nt][2], sc[nt][0], bi[nt][0]);
            v1.y = fmaf(d[mt][nt][3], sc[nt][1], bi[nt][1]);
            size_t r0 = (size_t)(crow + mt * 16) * SZ_N + ccol + nt * 8;
            size_t r1 = r0 + 8 * SZ_N;
            *reinterpret_cast<float2*>(out + r0) = v0;
            *reinterpret_cast<float2*>(out + r1) = v1;
        }
    }
}

// ---------------- launch ----------------
extern "C" void kernel_launch(void* const* d_in, const int* in_sizes, int n_in,
                              void* d_out, int out_size)
{
    const float* x  = (const float*)d_in[0];   // [4,2048,4096] fp32
    const int*   qw = (const int*)  d_in[1];   // [4096,4096] int32 in [-8,7]
    const float* ws = (const float*)d_in[2];   // [4096]
    const float* bs = (const float*)d_in[3];   // [4096]
    float* out = (float*)d_out;                // [4,2048,4096] fp32

    cudaFuncSetAttribute(gemm_hmma_kernel,
                         cudaFuncAttributeMaxDynamicSharedMemorySize, SMEM_TOTAL);

    cvt_all_kernel<<<(unsigned)((XC + WC) / 256), 256>>>(x, qw);

    dim3 grid(SZ_N / BN, SZ_M / BM);   // (16, 64), n-fastest
    gemm_hmma_kernel<<<grid, NTHREADS, SMEM_TOTAL>>>(ws, bs, out);
}

// round 5
// speedup vs baseline: 1.0378x; 1.0378x over previous
#include <cuda_runtime.h>
#include <cuda_fp16.h>
#include <cstdint>

// ---------------- problem sizes ----------------
#define SZ_M 8192   // 4 * 2048 rows of x
#define SZ_N 4096   // out features
#define SZ_K 4096   // in features

// ---------------- GEMM tiling ----------------
#define BM 128
#define BN 256
#define BK 128                // halves per stage (two 128B planes per row dim)
#define STAGES 2
#define KIT (SZ_K / BK)       // 32
#define NTHREADS 256          // 8 warps: 2(M) x 4(N), warp tile 64x64

// stage layout: [A plane0 16K][A plane1 16K][B plane0 32K][B plane1 32K] = 96KB
#define A_PLANE_BYTES (BM * 128)          // 16384
#define B_PLANE_BYTES (BN * 128)          // 32768
#define STAGE_A_BYTES (2 * A_PLANE_BYTES) // 32768
#define STAGE_B_BYTES (2 * B_PLANE_BYTES) // 65536
#define STAGE_BYTES   (STAGE_A_BYTES + STAGE_B_BYTES)   // 98304
#define SMEM_TOTAL    (STAGES * STAGE_BYTES)            // 196608

static_assert(SZ_M % BM == 0 && SZ_N % BN == 0 && SZ_K % BK == 0, "tiling");

// ---------------- scratch (no cudaMalloc allowed) ----------------
__device__ __align__(16) __half g_xh[(size_t)SZ_M * SZ_K];   // 64 MB
__device__ __align__(16) __half g_wh[(size_t)SZ_N * SZ_K];   // 32 MB

// ---------------- helpers ----------------
static __device__ __forceinline__ uint32_t smem_u32(const void* p) {
    uint32_t r;
    asm("{ .reg .u64 t; cvta.to.shared.u64 t, %1; cvt.u32.u64 %0, t; }"
        : "=r"(r) : "l"(p));
    return r;
}

static __device__ __forceinline__ void cp16(uint32_t dst, const void* src) {
    asm volatile("cp.async.cg.shared.global [%0], [%1], 16;"
                 :: "r"(dst), "l"(src) : "memory");
}

static __device__ __forceinline__ uint32_t sw128(uint32_t off) {
    return off ^ ((off >> 3) & 0x70);
}

static __device__ __forceinline__ void ldm_x4(uint32_t addr,
    uint32_t& r0, uint32_t& r1, uint32_t& r2, uint32_t& r3) {
    asm volatile("ldmatrix.sync.aligned.m8n8.x4.shared.b16 {%0,%1,%2,%3}, [%4];"
                 : "=r"(r0), "=r"(r1), "=r"(r2), "=r"(r3) : "r"(addr));
}

static __device__ __forceinline__ void mma16816(
    float& d0, float& d1, float& d2, float& d3,
    uint32_t a0, uint32_t a1, uint32_t a2, uint32_t a3,
    uint32_t b0, uint32_t b1) {
    asm volatile(
        "mma.sync.aligned.m16n8k16.row.col.f32.f16.f16.f32 "
        "{%0,%1,%2,%3}, {%4,%5,%6,%7}, {%8,%9}, {%0,%1,%2,%3};"
        : "+f"(d0), "+f"(d1), "+f"(d2), "+f"(d3)
        : "r"(a0), "r"(a1), "r"(a2), "r"(a3), "r"(b0), "r"(b1));
}

// ---------------- fused convert kernel ----------------
#define XC ((size_t)SZ_M * SZ_K / 4)
#define WC ((size_t)SZ_N * SZ_K / 4)

__global__ void __launch_bounds__(256) cvt_all_kernel(
    const float* __restrict__ x, const int* __restrict__ q)
{
    size_t i = (size_t)blockIdx.x * blockDim.x + threadIdx.x;
    if (i < XC) {
        float4 v = reinterpret_cast<const float4*>(x)[i];
        __half2 h0 = __floats2half2_rn(v.x, v.y);
        __half2 h1 = __floats2half2_rn(v.z, v.w);
        uint2 r;
        r.x = *reinterpret_cast<unsigned*>(&h0);
        r.y = *reinterpret_cast<unsigned*>(&h1);
        reinterpret_cast<uint2*>(g_xh)[i] = r;
    } else {
        size_t j = i - XC;
        int4 v = reinterpret_cast<const int4*>(q)[j];
        __half2 h0 = __halves2half2(__int2half_rn(v.x), __int2half_rn(v.y));
        __half2 h1 = __halves2half2(__int2half_rn(v.z), __int2half_rn(v.w));
        uint2 r;
        r.x = *reinterpret_cast<unsigned*>(&h0);
        r.y = *reinterpret_cast<unsigned*>(&h1);
        reinterpret_cast<uint2*>(g_wh)[j] = r;
    }
}

// ---------------- stage loader (256 threads) ----------------
// A: 2 planes x 1024 16B-chunks (8/thread). B: 2 planes x 2048 (16/thread).
static __device__ __forceinline__ void load_stage(
    uint32_t sb, int s, int m0, int n0, int kt, int tid)
{
    const uint32_t base = sb + (uint32_t)s * STAGE_BYTES;
    const int kh = kt * BK;

    #pragma unroll
    for (int i = 0; i < (2 * BM * 8) / NTHREADS; i++) {
        int c = tid + i * NTHREADS;
        int p = c >> 10;          // plane 0/1
        int j = c & 1023;
        int row = j >> 3, seg = j & 7;
        uint32_t off = (uint32_t)row * 128 + (uint32_t)seg * 16;
        cp16(base + (uint32_t)p * A_PLANE_BYTES + sw128(off),
             g_xh + (size_t)(m0 + row) * SZ_K + kh + p * 64 + seg * 8);
    }
    const uint32_t bbase = base + STAGE_A_BYTES;
    #pragma unroll
    for (int i = 0; i < (2 * BN * 8) / NTHREADS; i++) {
        int c = tid + i * NTHREADS;
        int p = c >> 11;          // plane 0/1
        int j = c & 2047;
        int row = j >> 3, seg = j & 7;
        uint32_t off = (uint32_t)row * 128 + (uint32_t)seg * 16;
        cp16(bbase + (uint32_t)p * B_PLANE_BYTES + sw128(off),
             g_wh + (size_t)(n0 + row) * SZ_K + kh + p * 64 + seg * 8);
    }
}

// ---------------- GEMM kernel ----------------
// 256 threads = 8 warps: wm = wid&1 (2 along M), wn = wid>>1 (4 along N).
// Warp tile 64(M) x 64(N): 4 m-tiles x 8 n-tiles, k-step 16 (ks = 0..7 per stage).
__global__ void __launch_bounds__(NTHREADS, 1)
gemm_hmma_kernel(const float* __restrict__ wscale,
                 const float* __restrict__ bias,
                 float* __restrict__ out)
{
    extern __shared__ char smem[];
    const uint32_t sb = smem_u32(smem);
    const int tid  = threadIdx.x;
    const int wid  = tid >> 5;
    const int lane = tid & 31;
    const int wm = wid & 1;
    const int wn = wid >> 1;
    const int n0 = blockIdx.x * BN;   // n-fastest: W stays L2-resident
    const int m0 = blockIdx.y * BM;

    const int l7   = lane & 7;
    const int hi8  = (lane >> 3) & 1;
    const int hi16 = lane >> 4;

    // A frag rows: wm*64 + mt*16 + hi8*8 + l7 ; k-byte within plane: ksl*32 + hi16*16
    const int arow_base = wm * 64 + hi8 * 8 + l7;
    const int akb_base  = hi16 * 16;
    // B frag rows: wn*64 + np*16 + hi16*8 + l7 ; k-byte within plane: ksl*32 + hi8*16
    const int brow_base = wn * 64 + hi16 * 8 + l7;
    const int bkb_base  = hi8 * 16;

    float d[4][8][4];
    #pragma unroll
    for (int i = 0; i < 4; i++)
        #pragma unroll
        for (int j = 0; j < 8; j++)
            #pragma unroll
            for (int c = 0; c < 4; c++) d[i][j][c] = 0.0f;

    // prefetch stage 0
    load_stage(sb, 0, m0, n0, 0, tid);
    asm volatile("cp.async.commit_group;" ::: "memory");

    #pragma unroll 1
    for (int kt = 0; kt < KIT; kt++) {
        const int s = kt & 1;
        asm volatile("cp.async.wait_group 0;" ::: "memory");
        __syncthreads();   // stage kt resident; stage kt-1 fully consumed

        if (kt + 1 < KIT) {
            load_stage(sb, s ^ 1, m0, n0, kt + 1, tid);
            asm volatile("cp.async.commit_group;" ::: "memory");
        }

        const uint32_t abase = sb + (uint32_t)s * STAGE_BYTES;
        const uint32_t bbase = abase + STAGE_A_BYTES;

        #pragma unroll
        for (int ks = 0; ks < BK / 16; ks++) {
            const uint32_t ap = abase + (uint32_t)(ks >> 2) * A_PLANE_BYTES;
            const uint32_t bp = bbase + (uint32_t)(ks >> 2) * B_PLANE_BYTES;
            const int ksl = ks & 3;

            uint32_t a[4][4];
            #pragma unroll
            for (int mt = 0; mt < 4; mt++) {
                uint32_t off = (uint32_t)(arow_base + mt * 16) * 128
                             + (uint32_t)(ksl * 32 + akb_base);
                ldm_x4(ap + sw128(off), a[mt][0], a[mt][1], a[mt][2], a[mt][3]);
            }
            uint32_t b[8][2];
            #pragma unroll
            for (int np = 0; np < 4; np++) {
                uint32_t off = (uint32_t)(brow_base + np * 16) * 128
                             + (uint32_t)(ksl * 32 + bkb_base);
                uint32_t r0, r1, r2, r3;
                ldm_x4(bp + sw128(off), r0, r1, r2, r3);
                b[np * 2 + 0][0] = r0; b[np * 2 + 0][1] = r1;
                b[np * 2 + 1][0] = r2; b[np * 2 + 1][1] = r3;
            }
            #pragma unroll
            for (int mt = 0; mt < 4; mt++)
                #pragma unroll
                for (int nt = 0; nt < 8; nt++)
                    mma16816(d[mt][nt][0], d[mt][nt][1], d[mt][nt][2], d[mt][nt][3],
                             a[mt][0], a[mt][1], a[mt][2], a[mt][3],
                             b[nt][0], b[nt][1]);
        }
    }

    // ---------------- epilogue: y = d * scale[col] + bias[col] ----------------
    const int crow = m0 + wm * 64 + (lane >> 2);       // + mt*16 (+8 for c2,c3)
    const int ccol = n0 + wn * 64 + (lane & 3) * 2;    // + nt*8

    float sc[8][2], bi[8][2];
    #pragma unroll
    for (int nt = 0; nt < 8; nt++) {
        sc[nt][0] = __ldg(wscale + ccol + nt * 8);
        sc[nt][1] = __ldg(wscale + ccol + nt * 8 + 1);
        bi[nt][0] = __ldg(bias   + ccol + nt * 8);
        bi[nt][1] = __ldg(bias   + ccol + nt * 8 + 1);
    }

    #pragma unroll
    for (int mt = 0; mt < 4; mt++) {
        #pragma unroll
        for (int nt = 0; nt < 8; nt++) {
            float2 v0, v1;
            v0.x = fmaf(d[mt][nt][0], sc[nt][0], bi[nt][0]);
            v0.y = fmaf(d[mt][nt][1], sc[nt][1], bi[nt][1]);
            v1.x = fmaf(d[mt][nt][2], sc[nt][0], bi[nt][0]);
            v1.y = fmaf(d[mt][nt][3], sc[nt][1], bi[nt][1]);
            size_t r0 = (size_t)(crow + mt * 16) * SZ_N + ccol + nt * 8;
            size_t r1 = r0 + 8 * SZ_N;
            *reinterpret_cast<float2*>(out + r0) = v0;
            *reinterpret_cast<float2*>(out + r1) = v1;
        }
    }
}

// ---------------- launch ----------------
extern "C" void kernel_launch(void* const* d_in, const int* in_sizes, int n_in,
                              void* d_out, int out_size)
{
    const float* x  = (const float*)d_in[0];   // [4,2048,4096] fp32
    const int*   qw = (const int*)  d_in[1];   // [4096,4096] int32 in [-8,7]
    const float* ws = (const float*)d_in[2];   // [4096]
    const float* bs = (const float*)d_in[3];   // [4096]
    float* out = (float*)d_out;                // [4,2048,4096] fp32

    cudaFuncSetAttribute(gemm_hmma_kernel,
                         cudaFuncAttributeMaxDynamicSharedMemorySize, SMEM_TOTAL);

    cvt_all_kernel<<<(unsigned)((XC + WC) / 256), 256>>>(x, qw);

    dim3 grid(SZ_N / BN, SZ_M / BM);   // (16, 64), n-fastest
    gemm_hmma_kernel<<<grid, NTHREADS, SMEM_TOTAL>>>(ws, bs, out);
}